// round 14
// baseline (speedup 1.0000x reference)
#include <cuda_runtime.h>
#include <cuda_fp16.h>
#include <math.h>
#include <stdint.h>

#define TT 512
#define BB 64
#define II 1024
#define HH 1024
#define G4 4096
#define GRID 128
#define HCH 8
#define NTHR 576          // 16 compute warps + 2 comm warps

// ---------------- device globals (no runtime allocation) -------------------
__device__ float  g_wi[(size_t)TT * BB * G4];
__device__ __half g_in16[(size_t)TT * BB * II];
__device__ __half g_w16[(size_t)II * G4];
__device__ __half g_hA[2][32 * HH];
__device__ __half g_hB[2][32 * HH];
__device__ float  g_hf[BB * HH];
__device__ float  g_c[BB * HH];
// per-CTA release flags; quarter q occupies flags[32q..32q+31] = one 128B line
__device__ __align__(128) unsigned g_flagA[128];
__device__ __align__(128) unsigned g_flagB[128];

__global__ void k_init() {
    int i = blockIdx.x * blockDim.x + threadIdx.x;
    if (i < 128) { g_flagA[i] = 0u; g_flagB[i] = 0u; }
    if (i < 32 * HH) {
        g_hA[0][i] = __float2half(0.f);
        g_hB[0][i] = __float2half(0.f);
    }
}

// ---------------- helpers ----------------------------------------------------
__device__ __forceinline__ float tanh_fast(float x) {
    float y; asm("tanh.approx.f32 %0, %1;" : "=f"(y) : "f"(x)); return y;
}
__device__ __forceinline__ void mma_f16(float* d, const uint32_t* a,
                                        uint32_t b0, uint32_t b1) {
    asm volatile(
        "mma.sync.aligned.m16n8k16.row.col.f32.f16.f16.f32 "
        "{%0,%1,%2,%3}, {%4,%5,%6,%7}, {%8,%9}, {%0,%1,%2,%3};"
        : "+f"(d[0]), "+f"(d[1]), "+f"(d[2]), "+f"(d[3])
        : "r"(a[0]), "r"(a[1]), "r"(a[2]), "r"(a[3]), "r"(b0), "r"(b1));
}
__device__ __forceinline__ void cp16(uint32_t dst, const void* src) {
    asm volatile("cp.async.cg.shared.global [%0], [%1], 16;" :: "r"(dst), "l"(src));
}
__device__ __forceinline__ uint32_t pack2(float a, float b) {
    __half2 h = __floats2half2_rn(a, b);
    return *(uint32_t*)&h;
}
__device__ __forceinline__ void mbar_wait(uint32_t mb, uint32_t ph) {
    asm volatile(
        "{\n\t.reg .pred P;\n"
        "W%=:\n\tmbarrier.try_wait.parity.acquire.cta.shared::cta.b64 P, [%0], %1;\n"
        "\t@P bra D%=;\n\tbra W%=;\nD%=:\n\t}"
        :: "r"(mb), "r"(ph) : "memory");
}

// comm service (whole warp): arm mbars + release own flag (lane 0), then all
// 32 lanes poll the 32 producer flags of quarter `rank`, fence, multicast.
__device__ __forceinline__ void comm_serve(uint32_t mb, unsigned* flags,
                                           int myidx, uint32_t buf,
                                           const char* hsrc, uint32_t rank,
                                           unsigned target, int lane) {
    if (lane == 0) {
#pragma unroll
        for (int r = 0; r < 4; r++)
            asm volatile("mbarrier.arrive.expect_tx.shared.b64 _, [%0], %1;"
                         :: "r"(mb + 8 * r), "r"(16384u) : "memory");
        asm volatile("st.release.gpu.global.u32 [%0], %1;"
                     :: "l"(&flags[myidx]), "r"(target) : "memory");
    }
    const unsigned* fp = &flags[rank * 32 + lane];
    unsigned v;
    bool done = false;
    do {
        asm volatile("ld.relaxed.gpu.global.u32 %0, [%1];"
                     : "=r"(v) : "l"(fp) : "memory");
        done = __all_sync(0xFFFFFFFFu, v >= target);
    } while (!done);
    asm volatile("fence.acq_rel.gpu;" ::: "memory");
    __syncwarp();
    if (lane == 0) {
        asm volatile(
            "cp.async.bulk.shared::cluster.global.mbarrier::complete_tx::bytes"
            ".multicast::cluster [%0], [%1], %2, [%3], %4;"
            :: "r"(buf + rank * 16384u), "l"(hsrc + rank * 16384u),
               "r"(16384u), "r"(mb + 8u * rank), "h"((unsigned short)0xF) : "memory");
    }
}

// ---------------- fp32 -> fp16 conversion pass ------------------------------
__global__ __launch_bounds__(256) void k_cvt(const float* __restrict__ in,
                                             const float* __restrict__ w) {
    const long long stride = (long long)gridDim.x * blockDim.x;
    long long i = (long long)blockIdx.x * blockDim.x + threadIdx.x;
    const long long nin = (long long)TT * BB * II / 8;
    const long long nw = (long long)II * G4 / 8;
    for (long long j = i; j < nin; j += stride) {
        float4 v0 = ((const float4*)in)[j * 2];
        float4 v1 = ((const float4*)in)[j * 2 + 1];
        ((uint4*)g_in16)[j] = make_uint4(pack2(v0.x, v0.y), pack2(v0.z, v0.w),
                                         pack2(v1.x, v1.y), pack2(v1.z, v1.w));
    }
    for (long long j = i; j < nw; j += stride) {
        float4 v0 = ((const float4*)w)[j * 2];
        float4 v1 = ((const float4*)w)[j * 2 + 1];
        ((uint4*)g_w16)[j] = make_uint4(pack2(v0.x, v0.y), pack2(v0.z, v0.w),
                                        pack2(v1.x, v1.y), pack2(v1.z, v1.w));
    }
}

// ---------------- wi GEMM (v3, unchanged/passing) ----------------------------
#define W3_AS 40
#define W3_BS 136

__global__ __launch_bounds__(256, 2) void k_wi(const float* __restrict__ bias) {
    __shared__ __half As[2 * 128 * W3_AS];
    __shared__ __half Bs[2 * 32 * W3_BS];

    const int tid = threadIdx.x;
    const int lane = tid & 31, wid = tid >> 5;
    const int g = lane >> 2, tg = lane & 3;
    const int wm = (wid & 1) * 64;
    const int wn = (wid >> 1) * 32;
    const size_t m0 = (size_t)blockIdx.y * 128;
    const int n0 = blockIdx.x * 128;

    uint32_t asb, bsb;
    asm("{ .reg .u64 t; cvta.to.shared.u64 t, %1; cvt.u32.u64 %0, t; }"
        : "=r"(asb) : "l"(As));
    asm("{ .reg .u64 t; cvta.to.shared.u64 t, %1; cvt.u32.u64 %0, t; }"
        : "=r"(bsb) : "l"(Bs));

    const int ar = tid >> 2, ac = (tid & 3) * 8;
    const int br = tid >> 4, bc = (tid & 15) * 8;
    const __half* asrc0 = &g_in16[(m0 + ar) * II + ac];
    const __half* asrc1 = &g_in16[(m0 + ar + 64) * II + ac];
    const __half* bsrc0 = &g_w16[(size_t)br * G4 + n0 + bc];
    const __half* bsrc1 = &g_w16[(size_t)(br + 16) * G4 + n0 + bc];
    const uint32_t adst0 = asb + (uint32_t)(ar * W3_AS + ac) * 2;
    const uint32_t adst1 = asb + (uint32_t)((ar + 64) * W3_AS + ac) * 2;
    const uint32_t bdst0 = bsb + (uint32_t)(br * W3_BS + bc) * 2;
    const uint32_t bdst1 = bsb + (uint32_t)((br + 16) * W3_BS + bc) * 2;
    const uint32_t ABUF = 128 * W3_AS * 2, BBUF = 32 * W3_BS * 2;

    cp16(adst0, asrc0); cp16(adst1, asrc1);
    cp16(bdst0, bsrc0); cp16(bdst1, bsrc1);
    asm volatile("cp.async.commit_group;");

    float acc[4][4][4] = {};
    const uint32_t a_lane = (uint32_t)((wm + (lane & 15)) * W3_AS + (lane >> 4) * 8) * 2;
    const uint32_t b_lane = (uint32_t)((lane & 15) * W3_BS + wn) * 2;

    for (int it = 0; it < 32; it++) {
        const uint32_t buf = it & 1;
        if (it + 1 < 32) {
            const uint32_t nb = (it + 1) & 1;
            const int k1 = (it + 1) * 32;
            cp16(adst0 + nb * ABUF, asrc0 + k1);
            cp16(adst1 + nb * ABUF, asrc1 + k1);
            cp16(bdst0 + nb * BBUF, bsrc0 + (size_t)k1 * G4);
            cp16(bdst1 + nb * BBUF, bsrc1 + (size_t)k1 * G4);
            asm volatile("cp.async.commit_group;");
            asm volatile("cp.async.wait_group 1;");
        } else {
            asm volatile("cp.async.wait_group 0;");
        }
        __syncthreads();

        const uint32_t ab = asb + buf * ABUF + a_lane;
        const uint32_t bb = bsb + buf * BBUF + b_lane;
#pragma unroll
        for (int s = 0; s < 2; s++) {
            uint32_t a[4][4];
#pragma unroll
            for (int mb = 0; mb < 4; mb++) {
                asm volatile(
                    "ldmatrix.sync.aligned.m8n8.x4.shared.b16 {%0,%1,%2,%3}, [%4];"
                    : "=r"(a[mb][0]), "=r"(a[mb][1]), "=r"(a[mb][2]), "=r"(a[mb][3])
                    : "r"(ab + (uint32_t)(mb * 16 * W3_AS + s * 16) * 2));
            }
#pragma unroll
            for (int nbt = 0; nbt < 4; nbt++) {
                uint32_t b0, b1;
                asm volatile(
                    "ldmatrix.sync.aligned.m8n8.x2.trans.shared.b16 {%0,%1}, [%2];"
                    : "=r"(b0), "=r"(b1)
                    : "r"(bb + (uint32_t)(s * 16 * W3_BS + nbt * 8) * 2));
#pragma unroll
                for (int mb = 0; mb < 4; mb++) mma_f16(acc[mb][nbt], a[mb], b0, b1);
            }
        }
        __syncthreads();
    }
#pragma unroll
    for (int mb = 0; mb < 4; mb++) {
#pragma unroll
        for (int nbt = 0; nbt < 4; nbt++) {
            int col = n0 + wn + nbt * 8 + 2 * tg;
            float b0 = __ldg(&bias[col]), b1 = __ldg(&bias[col + 1]);
            size_t r0 = (m0 + wm + mb * 16 + g) * G4 + col;
            size_t r1 = (m0 + wm + mb * 16 + g + 8) * G4 + col;
            *(float2*)&g_wi[r0] = make_float2(acc[mb][nbt][0] + b0, acc[mb][nbt][1] + b1);
            *(float2*)&g_wi[r1] = make_float2(acc[mb][nbt][2] + b0, acc[mb][nbt][3] + b1);
        }
    }
}

// ---------------- persistent recurrence (v14: flag signaling) ---------------
#define PRS_R   36
#define PR_KC   (32 * PRS_R)
#define PRB_OFF 36864
#define BUFA_OFF 73728
#define BUFB_OFF 139264
#define MB_OFF   204800
#define SLEN_OFF 204928
#define SMEM_BYTES 205184

__global__ __launch_bounds__(NTHR, 1) __cluster_dims__(4, 1, 1)
void k_rec(const float* __restrict__ Whh,
           const int* __restrict__ length,
           float* __restrict__ out) {
    extern __shared__ uint32_t dsm[];
    uint32_t* Wstage = dsm;
    float* prA = (float*)dsm;
    float* prB = (float*)((char*)dsm + PRB_OFF);
    int* slen = (int*)((char*)dsm + SLEN_OFF);

    const int tid = threadIdx.x;
    const int lane = tid & 31, wid = tid >> 5;
    const int g = lane >> 2, tg = lane & 3;
    const int mh = wid & 1;
    const int kc = wid >> 1;
    const int q = kc >> 1;
    const int hb = blockIdx.x * HCH;
    const int myidx = blockIdx.x;
    uint32_t rank;
    asm("mov.u32 %0, %%cluster_ctarank;" : "=r"(rank));

    if (tid < BB) slen[tid] = length[tid];

    // one-time: W slice -> fragment-order fp16 smem
    for (int w = tid; w < 64 * 2 * 32; w += NTHR) {
        int ln = w & 31;
        int wg = (w >> 5) & 1;
        int s = w >> 6;
        int colg = ln >> 2, ktg = ln & 3;
        uint32_t vals[4];
#pragma unroll
        for (int j = 0; j < 4; j++) {
            int nt = wg * 2 + (j >> 1);
            int bi = j & 1;
            int col = nt * 8 + colg;
            int k = s * 16 + ktg * 2 + bi * 8;
            size_t base = (size_t)(col >> 3) * HH + hb + (col & 7);
            vals[j] = pack2(__ldg(&Whh[(size_t)k * G4 + base]),
                            __ldg(&Whh[(size_t)(k + 1) * G4 + base]));
        }
        *(uint4*)&Wstage[w * 4] = make_uint4(vals[0], vals[1], vals[2], vals[3]);
    }
    __syncthreads();

    uint4 wr[8][2];
    if (wid < 16) {
#pragma unroll
        for (int s = 0; s < 8; s++)
#pragma unroll
            for (int wg = 0; wg < 2; wg++)
                wr[s][wg] = *(const uint4*)&Wstage[(((kc * 8 + s) * 2 + wg) * 32 + lane) * 4];
    }
    __syncthreads();

    uint32_t smem_base;
    asm("{ .reg .u64 t; cvta.to.shared.u64 t, %1; cvt.u32.u64 %0, t; }"
        : "=r"(smem_base) : "l"(dsm));
    const uint32_t bufA = smem_base + BUFA_OFF;
    const uint32_t bufB = smem_base + BUFB_OFF;
    const uint32_t mbA = smem_base + MB_OFF;
    const uint32_t mbB = smem_base + MB_OFF + 32;

    if (tid == 0) {
#pragma unroll
        for (int r = 0; r < 4; r++) {
            asm volatile("mbarrier.init.shared.b64 [%0], 1;" :: "r"(mbA + 8 * r) : "memory");
            asm volatile("mbarrier.init.shared.b64 [%0], 1;" :: "r"(mbB + 8 * r) : "memory");
        }
    }
    __syncthreads();
    if (tid == 0) {
#pragma unroll
        for (int r = 0; r < 4; r++) {
            asm volatile("mbarrier.arrive.expect_tx.shared.b64 _, [%0], %1;"
                         :: "r"(mbA + 8 * r), "r"(16384u) : "memory");
            asm volatile("mbarrier.arrive.expect_tx.shared.b64 _, [%0], %1;"
                         :: "r"(mbB + 8 * r), "r"(16384u) : "memory");
        }
    }
    __syncthreads();
    asm volatile("barrier.cluster.arrive.aligned;" ::: "memory");
    asm volatile("barrier.cluster.wait.aligned;" ::: "memory");

    // initial multicasts (h(0) = 0) by the two comm warps
    if (tid == 512) {
        asm volatile(
            "cp.async.bulk.shared::cluster.global.mbarrier::complete_tx::bytes"
            ".multicast::cluster [%0], [%1], %2, [%3], %4;"
            :: "r"(bufA + rank * 16384u), "l"((const char*)g_hA[0] + rank * 16384u),
               "r"(16384u), "r"(mbA + 8u * rank), "h"((unsigned short)0xF) : "memory");
    }
    if (tid == 544) {
        asm volatile(
            "cp.async.bulk.shared::cluster.global.mbarrier::complete_tx::bytes"
            ".multicast::cluster [%0], [%1], %2, [%3], %4;"
            :: "r"(bufB + rank * 16384u), "l"((const char*)g_hB[0] + rank * 16384u),
               "r"(16384u), "r"(mbB + 8u * rank), "h"((unsigned short)0xF) : "memory");
    }

    if (wid < 16) {
        // ================= compute warps =================
        const int rowoff = (lane & 7) + ((lane & 16) >> 1);
        const int ch = (mh << 1) + ((lane >> 3) & 1);
        const int pos = ((((rowoff & 1) << 2) | ch) ^ (rowoff >> 1));
        const uint32_t a_loff = (uint32_t)(kc * 8192 + (rowoff >> 1) * 128 + pos * 16);

        const int grp = tid >> 8;
        const int utid = tid & 255;
        const int um = utid >> 3, unn = utid & 7;
        const int kown = hb + unn;
        const uint32_t hoff = (uint32_t)((kown >> 1) * 128 +
            ((((((kown & 1) << 2) | (um >> 3))) ^ ((kown >> 1) & 7)) << 4) + (um & 7) * 2);
        const int batch = grp * 32 + um;
        const int mylen = slen[batch];
        float c_reg = 0.f, h_reg = 0.f;

        float wi_cur[4];
        const size_t wb = (size_t)batch * G4 + hb + unn;
#pragma unroll
        for (int gg = 0; gg < 4; gg++) wi_cur[gg] = __ldcs(&g_wi[wb + gg * HH]);

        for (int t = 0; t < TT; t++) {
            const uint32_t ph = (uint32_t)(t & 1);
            float h_out = 0.f;

            // ---- chain A ----
            mbar_wait(mbA + 8 * q, ph);
            {
                float acc[4][4] = {};
#pragma unroll
                for (int s = 0; s < 8; s++) {
                    uint32_t a[4];
                    asm volatile(
                        "ldmatrix.sync.aligned.m8n8.x4.trans.shared.b16 {%0,%1,%2,%3}, [%4];"
                        : "=r"(a[0]), "=r"(a[1]), "=r"(a[2]), "=r"(a[3])
                        : "r"(bufA + a_loff + s * 1024));
                    mma_f16(acc[0], a, wr[s][0].x, wr[s][0].y);
                    mma_f16(acc[1], a, wr[s][0].z, wr[s][0].w);
                    mma_f16(acc[2], a, wr[s][1].x, wr[s][1].y);
                    mma_f16(acc[3], a, wr[s][1].z, wr[s][1].w);
                }
                float* pk = prA + kc * PR_KC;
                int row = mh * 16 + g;
#pragma unroll
                for (int nt = 0; nt < 4; nt++) {
                    int c0 = nt * 8 + tg * 2;
                    pk[c0 * PRS_R + row]           = acc[nt][0];
                    pk[(c0 + 1) * PRS_R + row]     = acc[nt][1];
                    pk[c0 * PRS_R + row + 8]       = acc[nt][2];
                    pk[(c0 + 1) * PRS_R + row + 8] = acc[nt][3];
                }
            }
            asm volatile("bar.sync 4, 512;" ::: "memory");
            if (grp == 0) {
                float gate[4];
#pragma unroll
                for (int gg = 0; gg < 4; gg++) {
                    float v = wi_cur[gg];
                    int cw = (gg * 8 + unn) * PRS_R + um;
#pragma unroll
                    for (int c = 0; c < 8; c++) v += prA[c * PR_KC + cw];
                    gate[gg] = v;
                }
                float fs = __fdividef(1.f, 1.f + __expf(-(gate[0] + 1.f)));
                float is = __fdividef(1.f, 1.f + __expf(-gate[1]));
                float os = __fdividef(1.f, 1.f + __expf(-gate[2]));
                float gt = tanh_fast(gate[3]);
                float c2 = fs * c_reg + is * gt;
                float h2 = os * tanh_fast(c2);
                bool msk = t < mylen;
                if (msk) { c_reg = c2; h_reg = h2; }
                *(__half*)((char*)g_hA[1 - (t & 1)] + hoff) = __float2half(h_reg);
                h_out = msk ? h2 : 0.f;
                asm volatile("bar.arrive 1, 288;" ::: "memory");
            }

            // ---- chain B ----
            mbar_wait(mbB + 8 * q, ph);
            {
                float acc[4][4] = {};
#pragma unroll
                for (int s = 0; s < 8; s++) {
                    uint32_t a[4];
                    asm volatile(
                        "ldmatrix.sync.aligned.m8n8.x4.trans.shared.b16 {%0,%1,%2,%3}, [%4];"
                        : "=r"(a[0]), "=r"(a[1]), "=r"(a[2]), "=r"(a[3])
                        : "r"(bufB + a_loff + s * 1024));
                    mma_f16(acc[0], a, wr[s][0].x, wr[s][0].y);
                    mma_f16(acc[1], a, wr[s][0].z, wr[s][0].w);
                    mma_f16(acc[2], a, wr[s][1].x, wr[s][1].y);
                    mma_f16(acc[3], a, wr[s][1].z, wr[s][1].w);
                }
                float* pk = prB + kc * PR_KC;
                int row = mh * 16 + g;
#pragma unroll
                for (int nt = 0; nt < 4; nt++) {
                    int c0 = nt * 8 + tg * 2;
                    pk[c0 * PRS_R + row]           = acc[nt][0];
                    pk[(c0 + 1) * PRS_R + row]     = acc[nt][1];
                    pk[c0 * PRS_R + row + 8]       = acc[nt][2];
                    pk[(c0 + 1) * PRS_R + row + 8] = acc[nt][3];
                }
            }
            asm volatile("bar.sync 5, 512;" ::: "memory");
            if (grp == 1) {
                float gate[4];
#pragma unroll
                for (int gg = 0; gg < 4; gg++) {
                    float v = wi_cur[gg];
                    int cw = (gg * 8 + unn) * PRS_R + um;
#pragma unroll
                    for (int c = 0; c < 8; c++) v += prB[c * PR_KC + cw];
                    gate[gg] = v;
                }
                float fs = __fdividef(1.f, 1.f + __expf(-(gate[0] + 1.f)));
                float is = __fdividef(1.f, 1.f + __expf(-gate[1]));
                float os = __fdividef(1.f, 1.f + __expf(-gate[2]));
                float gt = tanh_fast(gate[3]);
                float c2 = fs * c_reg + is * gt;
                float h2 = os * tanh_fast(c2);
                bool msk = t < mylen;
                if (msk) { c_reg = c2; h_reg = h2; }
                *(__half*)((char*)g_hB[1 - (t & 1)] + hoff) = __float2half(h_reg);
                h_out = msk ? h2 : 0.f;
                asm volatile("bar.arrive 2, 288;" ::: "memory");
            }

            // ---- overlap tail: out store + wi prefetch -----------------------
            out[(size_t)t * BB * HH + (size_t)batch * HH + hb + unn] = h_out;
            if (t + 1 < TT) {
                const float* wit = g_wi + (size_t)(t + 1) * BB * G4;
#pragma unroll
                for (int gg = 0; gg < 4; gg++) wi_cur[gg] = __ldcs(&wit[wb + gg * HH]);
            }
        }

        size_t idx = (size_t)batch * HH + hb + unn;
        g_hf[idx] = h_reg;
        g_c[idx] = c_reg;
    } else if (wid == 16) {
        // ================= comm warp A =================
        for (int t = 0; t < TT; t++) {
            asm volatile("bar.sync 1, 288;" ::: "memory");
            if (t + 1 < TT)
                comm_serve(mbA, g_flagA, myidx, bufA,
                           (const char*)g_hA[1 - (t & 1)], rank,
                           (unsigned)(t + 1), lane);
        }
    } else {
        // ================= comm warp B =================
        for (int t = 0; t < TT; t++) {
            asm volatile("bar.sync 2, 288;" ::: "memory");
            if (t + 1 < TT)
                comm_serve(mbB, g_flagB, myidx, bufB,
                           (const char*)g_hB[1 - (t & 1)], rank,
                           (unsigned)(t + 1), lane);
        }
    }

    asm volatile("barrier.cluster.arrive.aligned;" ::: "memory");
    asm volatile("barrier.cluster.wait.aligned;" ::: "memory");
}

// ---------------- tail -------------------------------------------------------
__global__ void k_tail(float* __restrict__ out, long long out_size) {
    const long long base = (long long)TT * BB * HH;
    if (out_size < base + 2LL * BB * HH) return;
    int i = blockIdx.x * blockDim.x + threadIdx.x;
    if (i < BB * HH) {
        out[base + i] = g_hf[i];
        out[base + BB * HH + i] = g_c[i];
    }
}

// ---------------- launch -----------------------------------------------------
extern "C" void kernel_launch(void* const* d_in, const int* in_sizes, int n_in,
                              void* d_out, int out_size) {
    const float* input = (const float*)d_in[0];
    const int* length = (const int*)d_in[1];
    const float* whh = (const float*)d_in[3];
    const float* bias = (const float*)d_in[4];
    float* out = (float*)d_out;

    static bool attr_done = false;
    if (!attr_done) {
        cudaFuncSetAttribute(k_rec, cudaFuncAttributeMaxDynamicSharedMemorySize,
                             SMEM_BYTES);
        attr_done = true;
    }

    // order: init, cvt, wi, rec (4th — ncu samples launch #4), tail
    k_init<<<(32 * HH + 255) / 256, 256>>>();

    k_cvt<<<2048, 256>>>(input, (const float*)d_in[2]);

    dim3 gwi(G4 / 128, (TT * BB) / 128);
    k_wi<<<gwi, 256>>>(bias);

    k_rec<<<GRID, NTHR, SMEM_BYTES>>>(whh, length, out);

    k_tail<<<(BB * HH + 255) / 256, 256>>>(out, (long long)out_size);
}

// round 15
// speedup vs baseline: 1.9869x; 1.9869x over previous
#include <cuda_runtime.h>
#include <cuda_fp16.h>
#include <math.h>
#include <stdint.h>

#define TT 512
#define BB 64
#define II 1024
#define HH 1024
#define G4 4096
#define GRID 128
#define HCH 8
#define NTHR 576          // 16 compute warps + 2 comm warps

// ---------------- device globals (no runtime allocation) -------------------
__device__ float  g_wi[(size_t)TT * BB * G4];
__device__ __half g_in16[(size_t)TT * BB * II];
__device__ __half g_w16[(size_t)II * G4];
__device__ __half g_hA[2][32 * HH];
__device__ __half g_hB[2][32 * HH];
__device__ float  g_hf[BB * HH];
__device__ float  g_c[BB * HH];
// per-quarter release counters, 128B apart (counter q at [q*32])
__device__ unsigned g_barA4[128];
__device__ unsigned g_barB4[128];

__global__ void k_init() {
    int i = blockIdx.x * blockDim.x + threadIdx.x;
    if (i < 128) { g_barA4[i] = 0u; g_barB4[i] = 0u; }
    if (i < 32 * HH) {
        g_hA[0][i] = __float2half(0.f);
        g_hB[0][i] = __float2half(0.f);
    }
}

// ---------------- helpers ----------------------------------------------------
__device__ __forceinline__ float tanh_fast(float x) {
    float y; asm("tanh.approx.f32 %0, %1;" : "=f"(y) : "f"(x)); return y;
}
__device__ __forceinline__ void mma_f16(float* d, const uint32_t* a,
                                        uint32_t b0, uint32_t b1) {
    asm volatile(
        "mma.sync.aligned.m16n8k16.row.col.f32.f16.f16.f32 "
        "{%0,%1,%2,%3}, {%4,%5,%6,%7}, {%8,%9}, {%0,%1,%2,%3};"
        : "+f"(d[0]), "+f"(d[1]), "+f"(d[2]), "+f"(d[3])
        : "r"(a[0]), "r"(a[1]), "r"(a[2]), "r"(a[3]), "r"(b0), "r"(b1));
}
__device__ __forceinline__ void cp16(uint32_t dst, const void* src) {
    asm volatile("cp.async.cg.shared.global [%0], [%1], 16;" :: "r"(dst), "l"(src));
}
__device__ __forceinline__ uint32_t pack2(float a, float b) {
    __half2 h = __floats2half2_rn(a, b);
    return *(uint32_t*)&h;
}
__device__ __forceinline__ void mbar_wait(uint32_t mb, uint32_t ph) {
    asm volatile(
        "{\n\t.reg .pred P;\n"
        "W%=:\n\tmbarrier.try_wait.parity.acquire.cta.shared::cta.b64 P, [%0], %1;\n"
        "\t@P bra D%=;\n\tbra W%=;\nD%=:\n\t}"
        :: "r"(mb), "r"(ph) : "memory");
}

// comm service with per-quarter counters (r13-proven): arm mbars, release to
// counters[q_own*32], poll counters[rank*32] (32 producers of our multicast
// quarter), acquire, multicast.
__device__ __forceinline__ void comm_serve(uint32_t mb, unsigned* counters,
                                           int q_own, uint32_t buf,
                                           const char* hsrc, uint32_t rank,
                                           unsigned target32) {
#pragma unroll
    for (int r = 0; r < 4; r++)
        asm volatile("mbarrier.arrive.expect_tx.shared.b64 _, [%0], %1;"
                     :: "r"(mb + 8 * r), "r"(16384u) : "memory");
    asm volatile("red.release.gpu.global.add.u32 [%0], %1;"
                 :: "l"(&counters[q_own * 32]), "r"(1u) : "memory");
    unsigned v;
    do {
        asm volatile("ld.relaxed.gpu.global.u32 %0, [%1];"
                     : "=r"(v) : "l"(&counters[rank * 32]) : "memory");
    } while (v < target32);
    // counter is monotonic: one acquire load provides the ordering (no fence)
    asm volatile("ld.acquire.gpu.global.u32 %0, [%1];"
                 : "=r"(v) : "l"(&counters[rank * 32]) : "memory");
    asm volatile(
        "cp.async.bulk.shared::cluster.global.mbarrier::complete_tx::bytes"
        ".multicast::cluster [%0], [%1], %2, [%3], %4;"
        :: "r"(buf + rank * 16384u), "l"(hsrc + rank * 16384u),
           "r"(16384u), "r"(mb + 8u * rank), "h"((unsigned short)0xF) : "memory");
}

// ---------------- fp32 -> fp16 conversion pass ------------------------------
__global__ __launch_bounds__(256) void k_cvt(const float* __restrict__ in,
                                             const float* __restrict__ w) {
    const long long stride = (long long)gridDim.x * blockDim.x;
    long long i = (long long)blockIdx.x * blockDim.x + threadIdx.x;
    const long long nin = (long long)TT * BB * II / 8;
    const long long nw = (long long)II * G4 / 8;
    for (long long j = i; j < nin; j += stride) {
        float4 v0 = ((const float4*)in)[j * 2];
        float4 v1 = ((const float4*)in)[j * 2 + 1];
        ((uint4*)g_in16)[j] = make_uint4(pack2(v0.x, v0.y), pack2(v0.z, v0.w),
                                         pack2(v1.x, v1.y), pack2(v1.z, v1.w));
    }
    for (long long j = i; j < nw; j += stride) {
        float4 v0 = ((const float4*)w)[j * 2];
        float4 v1 = ((const float4*)w)[j * 2 + 1];
        ((uint4*)g_w16)[j] = make_uint4(pack2(v0.x, v0.y), pack2(v0.z, v0.w),
                                        pack2(v1.x, v1.y), pack2(v1.z, v1.w));
    }
}

// ---------------- wi GEMM (v3, unchanged/passing) ----------------------------
#define W3_AS 40
#define W3_BS 136

__global__ __launch_bounds__(256, 2) void k_wi(const float* __restrict__ bias) {
    __shared__ __half As[2 * 128 * W3_AS];
    __shared__ __half Bs[2 * 32 * W3_BS];

    const int tid = threadIdx.x;
    const int lane = tid & 31, wid = tid >> 5;
    const int g = lane >> 2, tg = lane & 3;
    const int wm = (wid & 1) * 64;
    const int wn = (wid >> 1) * 32;
    const size_t m0 = (size_t)blockIdx.y * 128;
    const int n0 = blockIdx.x * 128;

    uint32_t asb, bsb;
    asm("{ .reg .u64 t; cvta.to.shared.u64 t, %1; cvt.u32.u64 %0, t; }"
        : "=r"(asb) : "l"(As));
    asm("{ .reg .u64 t; cvta.to.shared.u64 t, %1; cvt.u32.u64 %0, t; }"
        : "=r"(bsb) : "l"(Bs));

    const int ar = tid >> 2, ac = (tid & 3) * 8;
    const int br = tid >> 4, bc = (tid & 15) * 8;
    const __half* asrc0 = &g_in16[(m0 + ar) * II + ac];
    const __half* asrc1 = &g_in16[(m0 + ar + 64) * II + ac];
    const __half* bsrc0 = &g_w16[(size_t)br * G4 + n0 + bc];
    const __half* bsrc1 = &g_w16[(size_t)(br + 16) * G4 + n0 + bc];
    const uint32_t adst0 = asb + (uint32_t)(ar * W3_AS + ac) * 2;
    const uint32_t adst1 = asb + (uint32_t)((ar + 64) * W3_AS + ac) * 2;
    const uint32_t bdst0 = bsb + (uint32_t)(br * W3_BS + bc) * 2;
    const uint32_t bdst1 = bsb + (uint32_t)((br + 16) * W3_BS + bc) * 2;
    const uint32_t ABUF = 128 * W3_AS * 2, BBUF = 32 * W3_BS * 2;

    cp16(adst0, asrc0); cp16(adst1, asrc1);
    cp16(bdst0, bsrc0); cp16(bdst1, bsrc1);
    asm volatile("cp.async.commit_group;");

    float acc[4][4][4] = {};
    const uint32_t a_lane = (uint32_t)((wm + (lane & 15)) * W3_AS + (lane >> 4) * 8) * 2;
    const uint32_t b_lane = (uint32_t)((lane & 15) * W3_BS + wn) * 2;

    for (int it = 0; it < 32; it++) {
        const uint32_t buf = it & 1;
        if (it + 1 < 32) {
            const uint32_t nb = (it + 1) & 1;
            const int k1 = (it + 1) * 32;
            cp16(adst0 + nb * ABUF, asrc0 + k1);
            cp16(adst1 + nb * ABUF, asrc1 + k1);
            cp16(bdst0 + nb * BBUF, bsrc0 + (size_t)k1 * G4);
            cp16(bdst1 + nb * BBUF, bsrc1 + (size_t)k1 * G4);
            asm volatile("cp.async.commit_group;");
            asm volatile("cp.async.wait_group 1;");
        } else {
            asm volatile("cp.async.wait_group 0;");
        }
        __syncthreads();

        const uint32_t ab = asb + buf * ABUF + a_lane;
        const uint32_t bb = bsb + buf * BBUF + b_lane;
#pragma unroll
        for (int s = 0; s < 2; s++) {
            uint32_t a[4][4];
#pragma unroll
            for (int mb = 0; mb < 4; mb++) {
                asm volatile(
                    "ldmatrix.sync.aligned.m8n8.x4.shared.b16 {%0,%1,%2,%3}, [%4];"
                    : "=r"(a[mb][0]), "=r"(a[mb][1]), "=r"(a[mb][2]), "=r"(a[mb][3])
                    : "r"(ab + (uint32_t)(mb * 16 * W3_AS + s * 16) * 2));
            }
#pragma unroll
            for (int nbt = 0; nbt < 4; nbt++) {
                uint32_t b0, b1;
                asm volatile(
                    "ldmatrix.sync.aligned.m8n8.x2.trans.shared.b16 {%0,%1}, [%2];"
                    : "=r"(b0), "=r"(b1)
                    : "r"(bb + (uint32_t)(s * 16 * W3_BS + nbt * 8) * 2));
#pragma unroll
                for (int mb = 0; mb < 4; mb++) mma_f16(acc[mb][nbt], a[mb], b0, b1);
            }
        }
        __syncthreads();
    }
#pragma unroll
    for (int mb = 0; mb < 4; mb++) {
#pragma unroll
        for (int nbt = 0; nbt < 4; nbt++) {
            int col = n0 + wn + nbt * 8 + 2 * tg;
            float b0 = __ldg(&bias[col]), b1 = __ldg(&bias[col + 1]);
            size_t r0 = (m0 + wm + mb * 16 + g) * G4 + col;
            size_t r1 = (m0 + wm + mb * 16 + g + 8) * G4 + col;
            *(float2*)&g_wi[r0] = make_float2(acc[mb][nbt][0] + b0, acc[mb][nbt][1] + b1);
            *(float2*)&g_wi[r1] = make_float2(acc[mb][nbt][2] + b0, acc[mb][nbt][3] + b1);
        }
    }
}

// ---------------- persistent recurrence (v15: r13 + split barriers) ---------
#define PRS_R   36
#define PR_KC   (32 * PRS_R)
#define PRB_OFF 36864
#define BUFA_OFF 73728
#define BUFB_OFF 139264
#define MB_OFF   204800
#define SLEN_OFF 204928
#define SMEM_BYTES 205184

__global__ __launch_bounds__(NTHR, 1) __cluster_dims__(4, 1, 1)
void k_rec(const float* __restrict__ Whh,
           const int* __restrict__ length,
           float* __restrict__ out) {
    extern __shared__ uint32_t dsm[];
    uint32_t* Wstage = dsm;
    float* prA = (float*)dsm;
    float* prB = (float*)((char*)dsm + PRB_OFF);
    int* slen = (int*)((char*)dsm + SLEN_OFF);

    const int tid = threadIdx.x;
    const int lane = tid & 31, wid = tid >> 5;
    const int g = lane >> 2, tg = lane & 3;
    const int mh = wid & 1;
    const int kc = wid >> 1;
    const int q = kc >> 1;
    const int hb = blockIdx.x * HCH;
    const int q_own = blockIdx.x >> 5;
    uint32_t rank;
    asm("mov.u32 %0, %%cluster_ctarank;" : "=r"(rank));

    if (tid < BB) slen[tid] = length[tid];

    // one-time: W slice -> fragment-order fp16 smem
    for (int w = tid; w < 64 * 2 * 32; w += NTHR) {
        int ln = w & 31;
        int wg = (w >> 5) & 1;
        int s = w >> 6;
        int colg = ln >> 2, ktg = ln & 3;
        uint32_t vals[4];
#pragma unroll
        for (int j = 0; j < 4; j++) {
            int nt = wg * 2 + (j >> 1);
            int bi = j & 1;
            int col = nt * 8 + colg;
            int k = s * 16 + ktg * 2 + bi * 8;
            size_t base = (size_t)(col >> 3) * HH + hb + (col & 7);
            vals[j] = pack2(__ldg(&Whh[(size_t)k * G4 + base]),
                            __ldg(&Whh[(size_t)(k + 1) * G4 + base]));
        }
        *(uint4*)&Wstage[w * 4] = make_uint4(vals[0], vals[1], vals[2], vals[3]);
    }
    __syncthreads();

    uint4 wr[8][2];
    if (wid < 16) {
#pragma unroll
        for (int s = 0; s < 8; s++)
#pragma unroll
            for (int wg = 0; wg < 2; wg++)
                wr[s][wg] = *(const uint4*)&Wstage[(((kc * 8 + s) * 2 + wg) * 32 + lane) * 4];
    }
    __syncthreads();

    uint32_t smem_base;
    asm("{ .reg .u64 t; cvta.to.shared.u64 t, %1; cvt.u32.u64 %0, t; }"
        : "=r"(smem_base) : "l"(dsm));
    const uint32_t bufA = smem_base + BUFA_OFF;
    const uint32_t bufB = smem_base + BUFB_OFF;
    const uint32_t mbA = smem_base + MB_OFF;
    const uint32_t mbB = smem_base + MB_OFF + 32;

    if (tid == 0) {
#pragma unroll
        for (int r = 0; r < 4; r++) {
            asm volatile("mbarrier.init.shared.b64 [%0], 1;" :: "r"(mbA + 8 * r) : "memory");
            asm volatile("mbarrier.init.shared.b64 [%0], 1;" :: "r"(mbB + 8 * r) : "memory");
        }
    }
    __syncthreads();
    if (tid == 0) {
#pragma unroll
        for (int r = 0; r < 4; r++) {
            asm volatile("mbarrier.arrive.expect_tx.shared.b64 _, [%0], %1;"
                         :: "r"(mbA + 8 * r), "r"(16384u) : "memory");
            asm volatile("mbarrier.arrive.expect_tx.shared.b64 _, [%0], %1;"
                         :: "r"(mbB + 8 * r), "r"(16384u) : "memory");
        }
    }
    __syncthreads();
    asm volatile("barrier.cluster.arrive.aligned;" ::: "memory");
    asm volatile("barrier.cluster.wait.aligned;" ::: "memory");

    // initial multicasts (h(0) = 0) by the two comm warps
    if (tid == 512) {
        asm volatile(
            "cp.async.bulk.shared::cluster.global.mbarrier::complete_tx::bytes"
            ".multicast::cluster [%0], [%1], %2, [%3], %4;"
            :: "r"(bufA + rank * 16384u), "l"((const char*)g_hA[0] + rank * 16384u),
               "r"(16384u), "r"(mbA + 8u * rank), "h"((unsigned short)0xF) : "memory");
    }
    if (tid == 544) {
        asm volatile(
            "cp.async.bulk.shared::cluster.global.mbarrier::complete_tx::bytes"
            ".multicast::cluster [%0], [%1], %2, [%3], %4;"
            :: "r"(bufB + rank * 16384u), "l"((const char*)g_hB[0] + rank * 16384u),
               "r"(16384u), "r"(mbB + 8u * rank), "h"((unsigned short)0xF) : "memory");
    }

    if (wid < 16) {
        // ================= compute warps =================
        const int rowoff = (lane & 7) + ((lane & 16) >> 1);
        const int ch = (mh << 1) + ((lane >> 3) & 1);
        const int pos = ((((rowoff & 1) << 2) | ch) ^ (rowoff >> 1));
        const uint32_t a_loff = (uint32_t)(kc * 8192 + (rowoff >> 1) * 128 + pos * 16);

        const int grp = tid >> 8;
        const int utid = tid & 255;
        const int um = utid >> 3, unn = utid & 7;
        const int kown = hb + unn;
        const uint32_t hoff = (uint32_t)((kown >> 1) * 128 +
            ((((((kown & 1) << 2) | (um >> 3))) ^ ((kown >> 1) & 7)) << 4) + (um & 7) * 2);
        const int batch = grp * 32 + um;
        const int mylen = slen[batch];
        float c_reg = 0.f, h_reg = 0.f;

        float wi_cur[4];
        const size_t wb = (size_t)batch * G4 + hb + unn;
#pragma unroll
        for (int gg = 0; gg < 4; gg++) wi_cur[gg] = __ldcs(&g_wi[wb + gg * HH]);

        for (int t = 0; t < TT; t++) {
            const uint32_t ph = (uint32_t)(t & 1);
            float h_out = 0.f;

            // ---- chain A ----
            mbar_wait(mbA + 8 * q, ph);
            {
                float acc[4][4] = {};
#pragma unroll
                for (int s = 0; s < 8; s++) {
                    uint32_t a[4];
                    asm volatile(
                        "ldmatrix.sync.aligned.m8n8.x4.trans.shared.b16 {%0,%1,%2,%3}, [%4];"
                        : "=r"(a[0]), "=r"(a[1]), "=r"(a[2]), "=r"(a[3])
                        : "r"(bufA + a_loff + s * 1024));
                    mma_f16(acc[0], a, wr[s][0].x, wr[s][0].y);
                    mma_f16(acc[1], a, wr[s][0].z, wr[s][0].w);
                    mma_f16(acc[2], a, wr[s][1].x, wr[s][1].y);
                    mma_f16(acc[3], a, wr[s][1].z, wr[s][1].w);
                }
                float* pk = prA + kc * PR_KC;
                int row = mh * 16 + g;
#pragma unroll
                for (int nt = 0; nt < 4; nt++) {
                    int c0 = nt * 8 + tg * 2;
                    pk[c0 * PRS_R + row]           = acc[nt][0];
                    pk[(c0 + 1) * PRS_R + row]     = acc[nt][1];
                    pk[c0 * PRS_R + row + 8]       = acc[nt][2];
                    pk[(c0 + 1) * PRS_R + row + 8] = acc[nt][3];
                }
            }
            // split barrier 4: grp1 arrives (non-blocking), grp0 syncs (reads prA)
            if (grp == 0) {
                asm volatile("bar.sync 4, 512;" ::: "memory");
                float gate[4];
#pragma unroll
                for (int gg = 0; gg < 4; gg++) {
                    float v = wi_cur[gg];
                    int cw = (gg * 8 + unn) * PRS_R + um;
#pragma unroll
                    for (int c = 0; c < 8; c++) v += prA[c * PR_KC + cw];
                    gate[gg] = v;
                }
                float fs = __fdividef(1.f, 1.f + __expf(-(gate[0] + 1.f)));
                float is = __fdividef(1.f, 1.f + __expf(-gate[1]));
                float os = __fdividef(1.f, 1.f + __expf(-gate[2]));
                float gt = tanh_fast(gate[3]);
                float c2 = fs * c_reg + is * gt;
                float h2 = os * tanh_fast(c2);
                bool msk = t < mylen;
                if (msk) { c_reg = c2; h_reg = h2; }
                *(__half*)((char*)g_hA[1 - (t & 1)] + hoff) = __float2half(h_reg);
                h_out = msk ? h2 : 0.f;
                asm volatile("bar.arrive 1, 288;" ::: "memory");
            } else {
                asm volatile("bar.arrive 4, 512;" ::: "memory");
            }

            // ---- chain B ----
            mbar_wait(mbB + 8 * q, ph);
            {
                float acc[4][4] = {};
#pragma unroll
                for (int s = 0; s < 8; s++) {
                    uint32_t a[4];
                    asm volatile(
                        "ldmatrix.sync.aligned.m8n8.x4.trans.shared.b16 {%0,%1,%2,%3}, [%4];"
                        : "=r"(a[0]), "=r"(a[1]), "=r"(a[2]), "=r"(a[3])
                        : "r"(bufB + a_loff + s * 1024));
                    mma_f16(acc[0], a, wr[s][0].x, wr[s][0].y);
                    mma_f16(acc[1], a, wr[s][0].z, wr[s][0].w);
                    mma_f16(acc[2], a, wr[s][1].x, wr[s][1].y);
                    mma_f16(acc[3], a, wr[s][1].z, wr[s][1].w);
                }
                float* pk = prB + kc * PR_KC;
                int row = mh * 16 + g;
#pragma unroll
                for (int nt = 0; nt < 4; nt++) {
                    int c0 = nt * 8 + tg * 2;
                    pk[c0 * PRS_R + row]           = acc[nt][0];
                    pk[(c0 + 1) * PRS_R + row]     = acc[nt][1];
                    pk[c0 * PRS_R + row + 8]       = acc[nt][2];
                    pk[(c0 + 1) * PRS_R + row + 8] = acc[nt][3];
                }
            }
            // split barrier 5: grp0 arrives (non-blocking), grp1 syncs (reads prB)
            if (grp == 1) {
                asm volatile("bar.sync 5, 512;" ::: "memory");
                float gate[4];
#pragma unroll
                for (int gg = 0; gg < 4; gg++) {
                    float v = wi_cur[gg];
                    int cw = (gg * 8 + unn) * PRS_R + um;
#pragma unroll
                    for (int c = 0; c < 8; c++) v += prB[c * PR_KC + cw];
                    gate[gg] = v;
                }
                float fs = __fdividef(1.f, 1.f + __expf(-(gate[0] + 1.f)));
                float is = __fdividef(1.f, 1.f + __expf(-gate[1]));
                float os = __fdividef(1.f, 1.f + __expf(-gate[2]));
                float gt = tanh_fast(gate[3]);
                float c2 = fs * c_reg + is * gt;
                float h2 = os * tanh_fast(c2);
                bool msk = t < mylen;
                if (msk) { c_reg = c2; h_reg = h2; }
                *(__half*)((char*)g_hB[1 - (t & 1)] + hoff) = __float2half(h_reg);
                h_out = msk ? h2 : 0.f;
                asm volatile("bar.arrive 2, 288;" ::: "memory");
            } else {
                asm volatile("bar.arrive 5, 512;" ::: "memory");
            }

            // ---- overlap tail: out store + wi prefetch -----------------------
            out[(size_t)t * BB * HH + (size_t)batch * HH + hb + unn] = h_out;
            if (t + 1 < TT) {
                const float* wit = g_wi + (size_t)(t + 1) * BB * G4;
#pragma unroll
                for (int gg = 0; gg < 4; gg++) wi_cur[gg] = __ldcs(&wit[wb + gg * HH]);
            }
        }

        size_t idx = (size_t)batch * HH + hb + unn;
        g_hf[idx] = h_reg;
        g_c[idx] = c_reg;
    } else if (wid == 16) {
        // ================= comm warp A =================
        for (int t = 0; t < TT; t++) {
            asm volatile("bar.sync 1, 288;" ::: "memory");
            if (lane == 0 && t + 1 < TT)
                comm_serve(mbA, g_barA4, q_own, bufA,
                           (const char*)g_hA[1 - (t & 1)], rank,
                           (unsigned)(t + 1) * 32u);
        }
    } else {
        // ================= comm warp B =================
        for (int t = 0; t < TT; t++) {
            asm volatile("bar.sync 2, 288;" ::: "memory");
            if (lane == 0 && t + 1 < TT)
                comm_serve(mbB, g_barB4, q_own, bufB,
                           (const char*)g_hB[1 - (t & 1)], rank,
                           (unsigned)(t + 1) * 32u);
        }
    }

    asm volatile("barrier.cluster.arrive.aligned;" ::: "memory");
    asm volatile("barrier.cluster.wait.aligned;" ::: "memory");
}

// ---------------- tail -------------------------------------------------------
__global__ void k_tail(float* __restrict__ out, long long out_size) {
    const long long base = (long long)TT * BB * HH;
    if (out_size < base + 2LL * BB * HH) return;
    int i = blockIdx.x * blockDim.x + threadIdx.x;
    if (i < BB * HH) {
        out[base + i] = g_hf[i];
        out[base + BB * HH + i] = g_c[i];
    }
}

// ---------------- launch -----------------------------------------------------
extern "C" void kernel_launch(void* const* d_in, const int* in_sizes, int n_in,
                              void* d_out, int out_size) {
    const float* input = (const float*)d_in[0];
    const int* length = (const int*)d_in[1];
    const float* whh = (const float*)d_in[3];
    const float* bias = (const float*)d_in[4];
    float* out = (float*)d_out;

    static bool attr_done = false;
    if (!attr_done) {
        cudaFuncSetAttribute(k_rec, cudaFuncAttributeMaxDynamicSharedMemorySize,
                             SMEM_BYTES);
        attr_done = true;
    }

    // order: init, cvt, wi, rec (4th — ncu samples launch #4), tail
    k_init<<<(32 * HH + 255) / 256, 256>>>();

    k_cvt<<<2048, 256>>>(input, (const float*)d_in[2]);

    dim3 gwi(G4 / 128, (TT * BB) / 128);
    k_wi<<<gwi, 256>>>(bias);

    k_rec<<<GRID, NTHR, SMEM_BYTES>>>(whh, length, out);

    k_tail<<<(BB * HH + 255) / 256, 256>>>(out, (long long)out_size);
}